// round 5
// baseline (speedup 1.0000x reference)
#include <cuda_runtime.h>
#include <math.h>

// ---------------- problem constants ----------------
#define BQ 2
#define CIN 256
#define COUT 256
#define HDIM 32
#define NH 8
#define NN 40962
#define NTOP 2562
#define WTOP 16
#define NDOWN 2562
#define WDOWN 19
#define PTOP (NTOP*WTOP)                 // 40992
#define MTOT (PTOP + NDOWN*WDOWN)        // 89670
#define MROWS (BQ*NN)                    // 81924
#define MLPH 512
#define BN_EPS 1e-5f
#define ATT_SCALE 0.17677669529663687f   // 32^-0.5
#define NPART 256
#define KMAX 32

// ---------------- scratch (static device, no runtime alloc) ----------------
__device__ float g_qkv[(size_t)MROWS*768];
__device__ float g_res[(size_t)MROWS*COUT];
__device__ float g_xw [(size_t)BQ*NH*MTOT*HDIM];
__device__ float g_xf [(size_t)MROWS*CIN];
__device__ float g_out[(size_t)MROWS*COUT];
__device__ float g_res2[(size_t)MROWS*COUT];
__device__ float g_Wm[CIN*COUT];
__device__ float g_bm[COUT];
__device__ float g_psum[NPART*COUT];
__device__ float g_psq [NPART*COUT];
__device__ float g_scale[COUT];
__device__ float g_shift[COUT];
__device__ int   g_is64;
__device__ int   g_top32 [NTOP*WTOP];
__device__ int   g_down32[NDOWN*WDOWN];
__device__ int   g_rev32 [(size_t)NN*KMAX];

// ---------------- index dtype sniffing + normalization ----------------
// If the index tensors are int64, the odd 32-bit words (high halves) are all 0
// (values < 90000 and non-negative). With int32 data, odd words are random
// valid indices — vanishing chance 1024 of them are all zero.
__global__ void detect_idx_kernel(const unsigned int* __restrict__ raw){
    if(threadIdx.x == 0 && blockIdx.x == 0){
        unsigned int acc = 0u;
        for(int i = 0; i < 1024; ++i) acc |= raw[2*i + 1];
        g_is64 = (acc == 0u) ? 1 : 0;
    }
}

__global__ void conv_idx_kernel(const void* __restrict__ src, int* __restrict__ dst, int n){
    int i = blockIdx.x*blockDim.x + threadIdx.x;
    if(i >= n) return;
    long long v;
    if(g_is64) v = ((const long long*)src)[i];
    else       v = (long long)((const int*)src)[i];
    if(v < 0) v = 0;
    if(v > (long long)0x7fffffff) v = 0x7fffffff;
    dst[i] = (int)v;
}

// ---------------- fold MLP: Wm = Wm1 @ Wm2, bm = bm1 @ Wm2 + bm2 ----------------
__global__ void fold_mlp_kernel(const float* __restrict__ Wm1, const float* __restrict__ Wm2,
                                const float* __restrict__ bm1, const float* __restrict__ bm2){
    int i = blockIdx.x;      // 0..255 output row
    int j = threadIdx.x;     // 0..255 output col
    float acc = 0.f;
    for(int h=0; h<MLPH; ++h){
        acc += __ldg(&Wm1[i*MLPH + h]) * __ldg(&Wm2[h*COUT + j]);
    }
    g_Wm[i*COUT + j] = acc;
    if(i == 0){
        float b = bm2[j];
        for(int h=0; h<MLPH; ++h) b += __ldg(&bm1[h]) * __ldg(&Wm2[h*COUT + j]);
        g_bm[j] = b;
    }
}

// ---------------- GEMM 1: qkv + res from x (A accessed transposed) ----------------
// A[m,k] = x[b, k, n] with m = b*NN + n.  Cols 0..767 -> Wqkv/g_qkv, 768..1023 -> Wres/g_res.
__global__ void gemm_qkvres_kernel(const float* __restrict__ x,
                                   const float* __restrict__ Wqkv, const float* __restrict__ bqkv,
                                   const float* __restrict__ Wres, const float* __restrict__ bres){
    __shared__ float As[16][64];
    __shared__ float Bs[16][64];
    const int m0 = blockIdx.x * 64;
    const int c0 = blockIdx.y * 64;
    const bool isres = (c0 >= 768);
    const float* W   = isres ? Wres : Wqkv;
    const float* bia = isres ? bres : bqkv;
    const int ldw    = isres ? COUT : 768;
    const int cW0    = isres ? c0 - 768 : c0;

    const int tid = threadIdx.x;
    const int tx = tid & 15, ty = tid >> 4;
    float acc[4][4];
    #pragma unroll
    for(int i=0;i<4;i++)
        #pragma unroll
        for(int j=0;j<4;j++) acc[i][j]=0.f;

    for(int kc=0; kc<CIN; kc+=16){
        #pragma unroll
        for(int i=0;i<4;i++){
            int id = tid + i*256;
            int k = id >> 6, ml = id & 63;
            int m = m0 + ml;
            float v = 0.f;
            if(m < MROWS){
                int b = (m >= NN) ? 1 : 0;
                int n = m - b*NN;
                v = x[((size_t)b*CIN + (kc+k))*NN + n];
            }
            As[k][ml] = v;
        }
        #pragma unroll
        for(int i=0;i<4;i++){
            int id = tid + i*256;
            int k = id >> 6, cl = id & 63;
            Bs[k][cl] = W[(size_t)(kc+k)*ldw + cW0 + cl];
        }
        __syncthreads();
        #pragma unroll
        for(int kk=0;kk<16;kk++){
            float4 a4 = *(const float4*)(&As[kk][ty*4]);
            float4 b4 = *(const float4*)(&Bs[kk][tx*4]);
            float av[4] = {a4.x,a4.y,a4.z,a4.w};
            float bv[4] = {b4.x,b4.y,b4.z,b4.w};
            #pragma unroll
            for(int i=0;i<4;i++)
                #pragma unroll
                for(int j=0;j<4;j++)
                    acc[i][j] += av[i]*bv[j];
        }
        __syncthreads();
    }

    const int c = cW0 + tx*4;
    float4 bb = *(const float4*)(bia + c);
    #pragma unroll
    for(int i=0;i<4;i++){
        int m = m0 + ty*4 + i;
        if(m >= MROWS) continue;
        float4 r = make_float4(acc[i][0]+bb.x, acc[i][1]+bb.y, acc[i][2]+bb.z, acc[i][3]+bb.w);
        if(!isres) *(float4*)(g_qkv + (size_t)m*768  + c) = r;
        else       *(float4*)(g_res + (size_t)m*COUT + c) = r;
    }
}

// ---------------- GEMM 2: row-major A (256-wide) @ W(256x256) + bias (+ add) ----------------
__global__ void gemm_rm_kernel(const float* __restrict__ A, const float* __restrict__ W,
                               const float* __restrict__ bias, const float* __restrict__ addsrc,
                               float* __restrict__ Dst){
    __shared__ float As[16][68];   // padded, rows 272B (16B aligned)
    __shared__ float Bs[16][64];
    const int m0 = blockIdx.x * 64;
    const int c0 = blockIdx.y * 64;
    const int tid = threadIdx.x;
    const int tx = tid & 15, ty = tid >> 4;
    float acc[4][4];
    #pragma unroll
    for(int i=0;i<4;i++)
        #pragma unroll
        for(int j=0;j<4;j++) acc[i][j]=0.f;

    for(int kc=0; kc<CIN; kc+=16){
        {
            int ml = tid >> 2, kq = tid & 3;
            int m = m0 + ml;
            float4 v = make_float4(0.f,0.f,0.f,0.f);
            if(m < MROWS) v = *(const float4*)(A + (size_t)m*CIN + kc + kq*4);
            As[kq*4+0][ml]=v.x; As[kq*4+1][ml]=v.y; As[kq*4+2][ml]=v.z; As[kq*4+3][ml]=v.w;
        }
        #pragma unroll
        for(int i=0;i<4;i++){
            int id = tid + i*256;
            int k = id >> 6, cl = id & 63;
            Bs[k][cl] = W[(size_t)(kc+k)*COUT + c0 + cl];
        }
        __syncthreads();
        #pragma unroll
        for(int kk=0;kk<16;kk++){
            float4 a4 = *(const float4*)(&As[kk][ty*4]);
            float4 b4 = *(const float4*)(&Bs[kk][tx*4]);
            float av[4] = {a4.x,a4.y,a4.z,a4.w};
            float bv[4] = {b4.x,b4.y,b4.z,b4.w};
            #pragma unroll
            for(int i=0;i<4;i++)
                #pragma unroll
                for(int j=0;j<4;j++)
                    acc[i][j] += av[i]*bv[j];
        }
        __syncthreads();
    }

    const int c = c0 + tx*4;
    float4 bb = *(const float4*)(bias + c);
    #pragma unroll
    for(int i=0;i<4;i++){
        int m = m0 + ty*4 + i;
        if(m >= MROWS) continue;
        float4 r = make_float4(acc[i][0]+bb.x, acc[i][1]+bb.y, acc[i][2]+bb.z, acc[i][3]+bb.w);
        if(addsrc){
            float4 ad = *(const float4*)(addsrc + (size_t)m*COUT + c);
            r.x+=ad.x; r.y+=ad.y; r.z+=ad.z; r.w+=ad.w;
        }
        *(float4*)(Dst + (size_t)m*COUT + c) = r;
    }
}

// ---------------- window attention: one warp per (window, b, h) ----------------
template<int W>
__global__ void attn_kernel(const int* __restrict__ widx, int poff){
    const int w  = blockIdx.x;
    const int bh = blockIdx.y;          // b*NH + h
    const int b  = bh >> 3;             // NH = 8
    const int h  = bh & 7;
    const int lane = threadIdx.x;

    __shared__ int    nidx[W];
    __shared__ float4 ks4[W*8];
    __shared__ float4 vs4[W*8];

    if(lane < W){
        int v = widx[w*W + lane];
        if((unsigned)v >= (unsigned)NN) v = 0;   // crash-proof clamp
        nidx[lane] = v;
    }
    __syncwarp();

    for(int t = lane; t < W*8; t += 32){
        int r = t >> 3, c4 = t & 7;
        size_t base = ((size_t)(b*NN + nidx[r]))*768 + h*HDIM + c4*4;
        ks4[t] = *(const float4*)(g_qkv + base + 256);
        vs4[t] = *(const float4*)(g_qkv + base + 512);
    }
    __syncwarp();

    if(lane < W){
        float4 qv[8];
        {
            size_t base = ((size_t)(b*NN + nidx[lane]))*768 + h*HDIM;
            const float4* qp = (const float4*)(g_qkv + base);
            #pragma unroll
            for(int c=0;c<8;c++) qv[c] = qp[c];
        }
        float p[W];
        float mx = -1e30f;
        #pragma unroll
        for(int j=0;j<W;j++){
            const float4* kp = ks4 + j*8;
            float s = 0.f;
            #pragma unroll
            for(int c=0;c<8;c++){
                float4 kk = kp[c];
                s += qv[c].x*kk.x + qv[c].y*kk.y + qv[c].z*kk.z + qv[c].w*kk.w;
            }
            s *= ATT_SCALE;
            p[j] = s;
            mx = fmaxf(mx, s);
        }
        float sum = 0.f;
        #pragma unroll
        for(int j=0;j<W;j++){ p[j] = __expf(p[j]-mx); sum += p[j]; }
        float inv = 1.f/sum;
        float4 accv[8];
        #pragma unroll
        for(int c=0;c<8;c++) accv[c] = make_float4(0.f,0.f,0.f,0.f);
        #pragma unroll
        for(int j=0;j<W;j++){
            float a = p[j]*inv;
            const float4* vp = vs4 + j*8;
            #pragma unroll
            for(int c=0;c<8;c++){
                float4 vv = vp[c];
                accv[c].x += a*vv.x; accv[c].y += a*vv.y;
                accv[c].z += a*vv.z; accv[c].w += a*vv.w;
            }
        }
        size_t o = (((size_t)bh)*MTOT + poff + (size_t)w*W + lane)*HDIM;
        float4* op = (float4*)(g_xw + o);
        #pragma unroll
        for(int c=0;c<8;c++) op[c] = accv[c];
    }
}

// ---------------- gather + average: xf[b,n, h*32+d] ----------------
__global__ void gather_avg_kernel(const int* __restrict__ ridx, const float* __restrict__ cnt_inv, int K){
    int gw = (blockIdx.x*blockDim.x + threadIdx.x) >> 5;
    int lane = threadIdx.x & 31;
    if(gw >= MROWS*NH) return;
    int h  = gw & 7;
    int bn = gw >> 3;
    int n  = bn % NN;
    int b  = bn / NN;
    float acc = 0.f;
    size_t base = ((size_t)(b*NH + h))*MTOT;
    for(int k=0;k<K;k++){
        int r = ridx[(size_t)n*K + k];
        if((unsigned)r < (unsigned)MTOT) acc += g_xw[(base + r)*HDIM + lane];
    }
    g_xf[((size_t)bn)*CIN + h*HDIM + lane] = acc * cnt_inv[n];
}

// ---------------- BN statistics (deterministic two-pass) ----------------
__global__ void bn_part_kernel(){
    int j = threadIdx.x, blk = blockIdx.x;
    const int rows_per = (MROWS + NPART - 1)/NPART;
    int r0 = blk*rows_per;
    int r1 = r0 + rows_per; if(r1 > MROWS) r1 = MROWS;
    float s = 0.f, sq = 0.f;
    for(int r=r0;r<r1;r++){
        float v = g_res2[(size_t)r*COUT + j];
        s += v; sq += v*v;
    }
    g_psum[blk*COUT + j] = s;
    g_psq [blk*COUT + j] = sq;
}

__global__ void bn_final_kernel(const float* __restrict__ gamma, const float* __restrict__ beta){
    int j = threadIdx.x;
    float s = 0.f, sq = 0.f;
    for(int p=0;p<NPART;p++){ s += g_psum[p*COUT + j]; sq += g_psq[p*COUT + j]; }
    float mean = s / (float)MROWS;
    float var  = sq / (float)MROWS - mean*mean;
    float sc = gamma[j] * rsqrtf(var + BN_EPS);
    g_scale[j] = sc;
    g_shift[j] = beta[j] - mean*sc;
}

// ---------------- final: out_t + bn, transposed write (B, OUT, N) ----------------
__global__ void final_out_kernel(float* __restrict__ dout){
    __shared__ float t[32][33];
    const int n0 = blockIdx.x * 32;
    const int by = blockIdx.y;
    const int b  = by >> 3;
    const int j0 = (by & 7) * 32;
    const int txx = threadIdx.x, tyy = threadIdx.y;

    const int j = j0 + txx;
    const float sc = g_scale[j], sh = g_shift[j];
    #pragma unroll
    for(int i=0;i<4;i++){
        int n = n0 + tyy + i*8;
        float v = 0.f;
        if(n < NN){
            size_t idx = ((size_t)(b*NN + n))*COUT + j;
            v = g_out[idx] + g_res2[idx]*sc + sh;
        }
        t[tyy + i*8][txx] = v;
    }
    __syncthreads();
    int n = n0 + txx;
    if(n < NN){
        #pragma unroll
        for(int i=0;i<4;i++){
            int jj = j0 + tyy + i*8;
            dout[((size_t)(b*COUT + jj))*NN + n] = t[txx][tyy + i*8];
        }
    }
}

// ---------------- launch ----------------
extern "C" void kernel_launch(void* const* d_in, const int* in_sizes, int n_in,
                              void* d_out, int out_size){
    (void)out_size;

    // ---- resolve inputs by element count (robust to dict vs sorted-key order) ----
    const int SZ_X = 20972544, SZ_WQKV = 196608, SZ_WM = 131072, SZ_WPR = 65536,
              SZ_BQKV = 768, SZ_BM1 = 512, SZ_CNT = 40962, SZ_TOP = 40992, SZ_DOWN = 48678;

    int ix=-1, iwqkv=-1, iwm1=-1, iwm2=-1, iwproj=-1, iwres=-1, ibqkv=-1, ibm1=-1,
        icnt=-1, itop=-1, idown=-1, irev=-1;
    int i256[8]; int n256 = 0;
    for(int i=0;i<n_in;i++){
        int s = in_sizes[i];
        if(s==SZ_X) ix=i;
        else if(s==SZ_WQKV) iwqkv=i;
        else if(s==SZ_WM){ if(iwm1<0) iwm1=i; else iwm2=i; }
        else if(s==SZ_WPR){ if(iwproj<0) iwproj=i; else iwres=i; }
        else if(s==SZ_BQKV) ibqkv=i;
        else if(s==SZ_BM1) ibm1=i;
        else if(s==SZ_CNT) icnt=i;
        else if(s==SZ_TOP) itop=i;
        else if(s==SZ_DOWN) idown=i;
        else if(s==256){ if(n256<8) i256[n256++]=i; }
        else if(s>SZ_CNT && (s % SZ_CNT)==0) irev=i;
    }

    int ibproj, ibres, ibm2, igamma, ibeta;
    bool resolved = (ix>=0 && iwqkv>=0 && iwm1>=0 && iwm2>=0 && iwproj>=0 && iwres>=0 &&
                     ibqkv>=0 && ibm1>=0 && icnt>=0 && itop>=0 && idown>=0 && irev>=0 && n256>=5);
    if(resolved){
        if(ix != 0){ // sorted-key order: beta, bm2, bproj, bres, gamma
            ibeta=i256[0]; ibm2=i256[1]; ibproj=i256[2]; ibres=i256[3]; igamma=i256[4];
        } else {     // dict order: bproj, bres, bm2, gamma, beta
            ibproj=i256[0]; ibres=i256[1]; ibm2=i256[2]; igamma=i256[3]; ibeta=i256[4];
        }
    } else {
        // fallback: dict insertion order
        ix=0; iwqkv=1; ibqkv=2; iwproj=3; ibproj=4; iwres=5; ibres=6;
        iwm1=7; ibm1=8; iwm2=9; ibm2=10; igamma=11; ibeta=12; icnt=13;
        itop=14; idown=15; irev=16;
    }

    const float* x     = (const float*)d_in[ix];
    const float* Wqkv  = (const float*)d_in[iwqkv];
    const float* bqkv  = (const float*)d_in[ibqkv];
    const float* Wproj = (const float*)d_in[iwproj];
    const float* bproj = (const float*)d_in[ibproj];
    const float* Wres  = (const float*)d_in[iwres];
    const float* bres  = (const float*)d_in[ibres];
    const float* Wm1   = (const float*)d_in[iwm1];
    const float* bm1   = (const float*)d_in[ibm1];
    const float* Wm2   = (const float*)d_in[iwm2];
    const float* bm2   = (const float*)d_in[ibm2];
    const float* gamma = (const float*)d_in[igamma];
    const float* beta  = (const float*)d_in[ibeta];
    const float* cnt_inv = (const float*)d_in[icnt];

    int K = in_sizes[irev] / NN;
    if(K < 1) K = 1;
    if(K > KMAX) K = KMAX;

    int* g_top32_p;  cudaGetSymbolAddress((void**)&g_top32_p,  g_top32);
    int* g_down32_p; cudaGetSymbolAddress((void**)&g_down32_p, g_down32);
    int* g_rev32_p;  cudaGetSymbolAddress((void**)&g_rev32_p,  g_rev32);
    float* g_xf_p;   cudaGetSymbolAddress((void**)&g_xf_p,   g_xf);
    float* g_out_p;  cudaGetSymbolAddress((void**)&g_out_p,  g_out);
    float* g_res_p;  cudaGetSymbolAddress((void**)&g_res_p,  g_res);
    float* g_res2_p; cudaGetSymbolAddress((void**)&g_res2_p, g_res2);
    float* g_Wm_p;   cudaGetSymbolAddress((void**)&g_Wm_p,   g_Wm);
    float* g_bm_p;   cudaGetSymbolAddress((void**)&g_bm_p,   g_bm);

    // 0. normalize index dtype (int32 or int64) into int32 scratch
    detect_idx_kernel<<<1, 32>>>((const unsigned int*)d_in[itop]);
    conv_idx_kernel<<<(NTOP*WTOP   + 255)/256, 256>>>(d_in[itop],  g_top32_p,  NTOP*WTOP);
    conv_idx_kernel<<<(NDOWN*WDOWN + 255)/256, 256>>>(d_in[idown], g_down32_p, NDOWN*WDOWN);
    conv_idx_kernel<<<(NN*K        + 255)/256, 256>>>(d_in[irev],  g_rev32_p,  NN*K);

    // 1. fold MLP weights
    fold_mlp_kernel<<<256, 256>>>(Wm1, Wm2, bm1, bm2);

    // 2. qkv + residual projection
    {
        dim3 grid((MROWS + 63)/64, 1024/64);
        gemm_qkvres_kernel<<<grid, 256>>>(x, Wqkv, bqkv, Wres, bres);
    }

    // 3. window attention (top 16-wide, down 19-wide)
    attn_kernel<WTOP> <<<dim3(NTOP,  BQ*NH), 32>>>(g_top32_p,  0);
    attn_kernel<WDOWN><<<dim3(NDOWN, BQ*NH), 32>>>(g_down32_p, PTOP);

    // 4. gather + count-average back to node order
    {
        long long warps = (long long)MROWS*NH;
        int blocks = (int)((warps*32 + 255)/256);
        gather_avg_kernel<<<blocks, 256>>>(g_rev32_p, cnt_inv, K);
    }

    // 5. out = xf @ Wproj + bproj + res
    {
        dim3 grid((MROWS + 63)/64, COUT/64);
        gemm_rm_kernel<<<grid, 256>>>(g_xf_p, Wproj, bproj, g_res_p, g_out_p);
    }

    // 6. res2 = out @ Wm + bm (folded MLP)
    {
        dim3 grid((MROWS + 63)/64, COUT/64);
        gemm_rm_kernel<<<grid, 256>>>(g_out_p, g_Wm_p, g_bm_p, nullptr, g_res2_p);
    }

    // 7-8. batch-norm statistics
    bn_part_kernel<<<NPART, 256>>>();
    bn_final_kernel<<<1, 256>>>(gamma, beta);

    // 9. final transposed output
    {
        dim3 grid((NN + 31)/32, BQ*(COUT/32));
        final_out_kernel<<<grid, dim3(32,8)>>>((float*)d_out);
    }
}

// round 8
// speedup vs baseline: 1.6950x; 1.6950x over previous
#include <cuda_runtime.h>
#include <math.h>
#include <stdint.h>

// ---------------- problem constants ----------------
#define BQ 2
#define CIN 256
#define COUT 256
#define HDIM 32
#define NH 8
#define NN 40962
#define NTOP 2562
#define WTOP 16
#define NDOWN 2562
#define WDOWN 19
#define PTOP (NTOP*WTOP)                 // 40992
#define MTOT (PTOP + NDOWN*WDOWN)        // 89670
#define MROWS (BQ*NN)                    // 81924
#define MLPH 512
#define BN_EPS 1e-5f
#define ATT_SCALE 0.17677669529663687f   // 32^-0.5
#define NPART 256
#define KMAX 32

// GEMM tile config
#define SSTR 24                           // smem row stride (floats), conflict-free for LDS.64 frags
#define TILE_FLOATS (128*SSTR)            // 3072 floats per buffer
#define SMEM_BYTES (4*TILE_FLOATS*4)      // As0,As1,Bs0,Bs1 = 49152 B

// ---------------- scratch (static device, no runtime alloc) ----------------
__device__ float g_qkv[(size_t)MROWS*768];
__device__ float g_res[(size_t)MROWS*COUT];
__device__ float g_xw [(size_t)BQ*NH*MTOT*HDIM];
__device__ float g_xf [(size_t)MROWS*CIN];
__device__ float g_out[(size_t)MROWS*COUT];
__device__ float g_res2[(size_t)MROWS*COUT];
__device__ float g_Wm[CIN*COUT];
__device__ float g_bm[COUT];
__device__ float g_psum[NPART*COUT];
__device__ float g_psq [NPART*COUT];
__device__ float g_scale[COUT];
__device__ float g_shift[COUT];
__device__ int   g_is64;
__device__ int   g_top32 [NTOP*WTOP];
__device__ int   g_down32[NDOWN*WDOWN];
__device__ int   g_rev32 [(size_t)NN*KMAX];

// ---------------- helpers ----------------
__device__ __forceinline__ float tf32r(float x){
    uint32_t u; asm("cvt.rna.tf32.f32 %0, %1;" : "=r"(u) : "f"(x));
    return __uint_as_float(u);
}

__device__ __forceinline__ void mma_tf32(float4& d, float2 A0, float2 A1, float2 B0){
    uint32_t a0=__float_as_uint(A0.x), a1=__float_as_uint(A1.x),
             a2=__float_as_uint(A0.y), a3=__float_as_uint(A1.y),
             b0=__float_as_uint(B0.x), b1=__float_as_uint(B0.y);
    asm volatile("mma.sync.aligned.m16n8k8.row.col.f32.tf32.tf32.f32 "
        "{%0,%1,%2,%3},{%4,%5,%6,%7},{%8,%9},{%0,%1,%2,%3};"
        : "+f"(d.x),"+f"(d.y),"+f"(d.z),"+f"(d.w)
        : "r"(a0),"r"(a1),"r"(a2),"r"(a3),"r"(b0),"r"(b1));
}

// compute 2 k-steps of mma over the staged 128x16 (A) and 128x16 (B) tiles
__device__ __forceinline__ void mma_tile(const float* __restrict__ As, const float* __restrict__ Bs,
                                         int warp_m, int warp_n, int group, int qc,
                                         float4 acc[4][4]){
    #pragma unroll
    for(int s=0; s<2; ++s){
        float2 Af[4][2];
        #pragma unroll
        for(int mt=0; mt<4; ++mt){
            int r = warp_m*64 + mt*16 + group;
            Af[mt][0] = *(const float2*)(As + r*SSTR     + s*8 + qc*2);
            Af[mt][1] = *(const float2*)(As + (r+8)*SSTR + s*8 + qc*2);
        }
        float2 Bf[4];
        #pragma unroll
        for(int nt=0; nt<4; ++nt){
            int r = warp_n*32 + nt*8 + group;
            Bf[nt] = *(const float2*)(Bs + r*SSTR + s*8 + qc*2);
        }
        #pragma unroll
        for(int mt=0; mt<4; ++mt)
            #pragma unroll
            for(int nt=0; nt<4; ++nt)
                mma_tf32(acc[mt][nt], Af[mt][0], Af[mt][1], Bf[nt]);
    }
}

__device__ __forceinline__ void sts_tile(float* __restrict__ S, int row, int h, const float v[8]){
    float4 p0 = make_float4(tf32r(v[0]),tf32r(v[1]),tf32r(v[2]),tf32r(v[3]));
    float4 p1 = make_float4(tf32r(v[4]),tf32r(v[5]),tf32r(v[6]),tf32r(v[7]));
    *(float4*)(S + row*SSTR + h*8)     = p0;
    *(float4*)(S + row*SSTR + h*8 + 4) = p1;
}

// ---------------- index dtype sniffing + normalization ----------------
__global__ void detect_idx_kernel(const unsigned int* __restrict__ raw){
    if(threadIdx.x == 0 && blockIdx.x == 0){
        unsigned int acc = 0u;
        for(int i = 0; i < 1024; ++i) acc |= raw[2*i + 1];
        g_is64 = (acc == 0u) ? 1 : 0;
    }
}

__global__ void conv_idx_kernel(const void* __restrict__ src, int* __restrict__ dst, int n){
    int i = blockIdx.x*blockDim.x + threadIdx.x;
    if(i >= n) return;
    long long v;
    if(g_is64) v = ((const long long*)src)[i];
    else       v = (long long)((const int*)src)[i];
    if(v < 0) v = 0;
    if(v > (long long)0x7fffffff) v = 0x7fffffff;
    dst[i] = (int)v;
}

// ---------------- fold MLP: Wm = Wm1 @ Wm2, bm = bm1 @ Wm2 + bm2 ----------------
__global__ void fold_mlp_kernel(const float* __restrict__ Wm1, const float* __restrict__ Wm2,
                                const float* __restrict__ bm1, const float* __restrict__ bm2){
    int i = blockIdx.x;
    int j = threadIdx.x;
    float acc = 0.f;
    for(int h=0; h<MLPH; ++h){
        acc += __ldg(&Wm1[i*MLPH + h]) * __ldg(&Wm2[h*COUT + j]);
    }
    g_Wm[i*COUT + j] = acc;
    if(i == 0){
        float b = bm2[j];
        for(int h=0; h<MLPH; ++h) b += __ldg(&bm1[h]) * __ldg(&Wm2[h*COUT + j]);
        g_bm[j] = b;
    }
}

// ---------------- tf32 GEMM 1: qkv + res from x (A accessed transposed) ----------------
// out[m, c], c in [0,1024): 0..767 -> Wqkv/g_qkv, 768..1023 -> Wres/g_res.
__global__ __launch_bounds__(256, 2)
void gemm_qkvres_tc(const float* __restrict__ x,
                    const float* __restrict__ Wqkv, const float* __restrict__ bqkv,
                    const float* __restrict__ Wres, const float* __restrict__ bres){
    extern __shared__ float sm[];
    float* Abuf[2] = { sm, sm + TILE_FLOATS };
    float* Bbuf[2] = { sm + 2*TILE_FLOATS, sm + 3*TILE_FLOATS };

    const int m0 = blockIdx.x * 128;
    const int c0 = blockIdx.y * 128;
    const bool isres = (c0 >= 768);
    const float* W   = isres ? Wres : Wqkv;
    const float* bia = isres ? bres : bqkv;
    const int ldw    = isres ? COUT : 768;
    const int cW0    = isres ? c0 - 768 : c0;

    const int tid = threadIdx.x;
    const int wid = tid >> 5, lane = tid & 31;
    const int warp_m = wid >> 2, warp_n = wid & 3;
    const int group = lane >> 2, qc = lane & 3;
    const int lm = tid & 127, h = tid >> 7;

    float4 acc[4][4];
    #pragma unroll
    for(int i=0;i<4;i++)
        #pragma unroll
        for(int j=0;j<4;j++) acc[i][j] = make_float4(0.f,0.f,0.f,0.f);

    float av[8], bv[8];
    // prologue: stage kc=0
    {
        int m = m0 + lm;
        if(m < MROWS){
            int b = (m >= NN) ? 1 : 0;
            int n = m - b*NN;
            const float* xp = x + ((size_t)b*CIN + h*8)*NN + n;
            #pragma unroll
            for(int j=0;j<8;j++) av[j] = xp[(size_t)j*NN];
        } else {
            #pragma unroll
            for(int j=0;j<8;j++) av[j] = 0.f;
        }
        const float* wp = W + (size_t)(h*8)*ldw + cW0 + lm;
        #pragma unroll
        for(int j=0;j<8;j++) bv[j] = wp[(size_t)j*ldw];
        sts_tile(Abuf[0], lm, h, av);
        sts_tile(Bbuf[0], lm, h, bv);
    }
    __syncthreads();

    for(int t=0; t<16; ++t){
        int cur = t & 1, nxt = (t+1) & 1;
        if(t+1 < 16){
            int kc = (t+1)*16;
            int m = m0 + lm;
            if(m < MROWS){
                int b = (m >= NN) ? 1 : 0;
                int n = m - b*NN;
                const float* xp = x + ((size_t)b*CIN + kc + h*8)*NN + n;
                #pragma unroll
                for(int j=0;j<8;j++) av[j] = xp[(size_t)j*NN];
            } else {
                #pragma unroll
                for(int j=0;j<8;j++) av[j] = 0.f;
            }
            const float* wp = W + (size_t)(kc + h*8)*ldw + cW0 + lm;
            #pragma unroll
            for(int j=0;j<8;j++) bv[j] = wp[(size_t)j*ldw];
        }
        mma_tile(Abuf[cur], Bbuf[cur], warp_m, warp_n, group, qc, acc);
        if(t+1 < 16){
            sts_tile(Abuf[nxt], lm, h, av);
            sts_tile(Bbuf[nxt], lm, h, bv);
        }
        __syncthreads();
    }

    // epilogue
    #pragma unroll
    for(int nt=0; nt<4; ++nt){
        int cw = cW0 + warp_n*32 + nt*8 + qc*2;
        float2 bb = *(const float2*)(bia + cw);
        #pragma unroll
        for(int mt=0; mt<4; ++mt){
            int r0 = m0 + warp_m*64 + mt*16 + group;
            float4 a = acc[mt][nt];
            if(r0 < MROWS){
                float2 v = make_float2(a.x + bb.x, a.y + bb.y);
                if(!isres) *(float2*)(g_qkv + (size_t)r0*768  + cw) = v;
                else       *(float2*)(g_res + (size_t)r0*COUT + cw) = v;
            }
            int r1 = r0 + 8;
            if(r1 < MROWS){
                float2 v = make_float2(a.z + bb.x, a.w + bb.y);
                if(!isres) *(float2*)(g_qkv + (size_t)r1*768  + cw) = v;
                else       *(float2*)(g_res + (size_t)r1*COUT + cw) = v;
            }
        }
    }
}

// ---------------- tf32 GEMM 2: row-major A(m,256) @ W(256x256) + bias (+ add) ----------------
__global__ __launch_bounds__(256, 2)
void gemm_rm_tc(const float* __restrict__ A, const float* __restrict__ W,
                const float* __restrict__ bias, const float* __restrict__ addsrc,
                float* __restrict__ Dst){
    extern __shared__ float sm[];
    float* Abuf[2] = { sm, sm + TILE_FLOATS };
    float* Bbuf[2] = { sm + 2*TILE_FLOATS, sm + 3*TILE_FLOATS };

    const int m0 = blockIdx.x * 128;
    const int c0 = blockIdx.y * 128;
    const int tid = threadIdx.x;
    const int wid = tid >> 5, lane = tid & 31;
    const int warp_m = wid >> 2, warp_n = wid & 3;
    const int group = lane >> 2, qc = lane & 3;
    const int lm = tid & 127, h = tid >> 7;

    float4 acc[4][4];
    #pragma unroll
    for(int i=0;i<4;i++)
        #pragma unroll
        for(int j=0;j<4;j++) acc[i][j] = make_float4(0.f,0.f,0.f,0.f);

    float av[8], bv[8];
    {
        int m = m0 + lm;
        if(m < MROWS){
            float4 v0 = *(const float4*)(A + (size_t)m*CIN + h*8);
            float4 v1 = *(const float4*)(A + (size_t)m*CIN + h*8 + 4);
            av[0]=v0.x; av[1]=v0.y; av[2]=v0.z; av[3]=v0.w;
            av[4]=v1.x; av[5]=v1.y; av[6]=v1.z; av[7]=v1.w;
        } else {
            #pragma unroll
            for(int j=0;j<8;j++) av[j] = 0.f;
        }
        const float* wp = W + (size_t)(h*8)*COUT + c0 + lm;
        #pragma unroll
        for(int j=0;j<8;j++) bv[j] = wp[(size_t)j*COUT];
        sts_tile(Abuf[0], lm, h, av);
        sts_tile(Bbuf[0], lm, h, bv);
    }
    __syncthreads();

    for(int t=0; t<16; ++t){
        int cur = t & 1, nxt = (t+1) & 1;
        if(t+1 < 16){
            int kc = (t+1)*16;
            int m = m0 + lm;
            if(m < MROWS){
                float4 v0 = *(const float4*)(A + (size_t)m*CIN + kc + h*8);
                float4 v1 = *(const float4*)(A + (size_t)m*CIN + kc + h*8 + 4);
                av[0]=v0.x; av[1]=v0.y; av[2]=v0.z; av[3]=v0.w;
                av[4]=v1.x; av[5]=v1.y; av[6]=v1.z; av[7]=v1.w;
            } else {
                #pragma unroll
                for(int j=0;j<8;j++) av[j] = 0.f;
            }
            const float* wp = W + (size_t)(kc + h*8)*COUT + c0 + lm;
            #pragma unroll
            for(int j=0;j<8;j++) bv[j] = wp[(size_t)j*COUT];
        }
        mma_tile(Abuf[cur], Bbuf[cur], warp_m, warp_n, group, qc, acc);
        if(t+1 < 16){
            sts_tile(Abuf[nxt], lm, h, av);
            sts_tile(Bbuf[nxt], lm, h, bv);
        }
        __syncthreads();
    }

    #pragma unroll
    for(int nt=0; nt<4; ++nt){
        int cw = c0 + warp_n*32 + nt*8 + qc*2;
        float2 bb = *(const float2*)(bias + cw);
        #pragma unroll
        for(int mt=0; mt<4; ++mt){
            int r0 = m0 + warp_m*64 + mt*16 + group;
            float4 a = acc[mt][nt];
            if(r0 < MROWS){
                float2 v = make_float2(a.x + bb.x, a.y + bb.y);
                if(addsrc){
                    float2 ad = *(const float2*)(addsrc + (size_t)r0*COUT + cw);
                    v.x += ad.x; v.y += ad.y;
                }
                *(float2*)(Dst + (size_t)r0*COUT + cw) = v;
            }
            int r1 = r0 + 8;
            if(r1 < MROWS){
                float2 v = make_float2(a.z + bb.x, a.w + bb.y);
                if(addsrc){
                    float2 ad = *(const float2*)(addsrc + (size_t)r1*COUT + cw);
                    v.x += ad.x; v.y += ad.y;
                }
                *(float2*)(Dst + (size_t)r1*COUT + cw) = v;
            }
        }
    }
}

// ---------------- window attention: one warp per (window, b, h) ----------------
template<int W>
__global__ void attn_kernel(const int* __restrict__ widx, int poff){
    const int w  = blockIdx.x;
    const int bh = blockIdx.y;
    const int b  = bh >> 3;
    const int h  = bh & 7;
    const int lane = threadIdx.x;

    __shared__ int    nidx[W];
    __shared__ float4 ks4[W*8];
    __shared__ float4 vs4[W*8];

    if(lane < W){
        int v = widx[w*W + lane];
        if((unsigned)v >= (unsigned)NN) v = 0;
        nidx[lane] = v;
    }
    __syncwarp();

    for(int t = lane; t < W*8; t += 32){
        int r = t >> 3, c4 = t & 7;
        size_t base = ((size_t)(b*NN + nidx[r]))*768 + h*HDIM + c4*4;
        ks4[t] = *(const float4*)(g_qkv + base + 256);
        vs4[t] = *(const float4*)(g_qkv + base + 512);
    }
    __syncwarp();

    if(lane < W){
        float4 qv[8];
        {
            size_t base = ((size_t)(b*NN + nidx[lane]))*768 + h*HDIM;
            const float4* qp = (const float4*)(g_qkv + base);
            #pragma unroll
            for(int c=0;c<8;c++) qv[c] = qp[c];
        }
        float p[W];
        float mx = -1e30f;
        #pragma unroll
        for(int j=0;j<W;j++){
            const float4* kp = ks4 + j*8;
            float s = 0.f;
            #pragma unroll
            for(int c=0;c<8;c++){
                float4 kk = kp[c];
                s += qv[c].x*kk.x + qv[c].y*kk.y + qv[c].z*kk.z + qv[c].w*kk.w;
            }
            s *= ATT_SCALE;
            p[j] = s;
            mx = fmaxf(mx, s);
        }
        float sum = 0.f;
        #pragma unroll
        for(int j=0;j<W;j++){ p[j] = __expf(p[j]-mx); sum += p[j]; }
        float inv = 1.f/sum;
        float4 accv[8];
        #pragma unroll
        for(int c=0;c<8;c++) accv[c] = make_float4(0.f,0.f,0.f,0.f);
        #pragma unroll
        for(int j=0;j<W;j++){
            float a = p[j]*inv;
            const float4* vp = vs4 + j*8;
            #pragma unroll
            for(int c=0;c<8;c++){
                float4 vv = vp[c];
                accv[c].x += a*vv.x; accv[c].y += a*vv.y;
                accv[c].z += a*vv.z; accv[c].w += a*vv.w;
            }
        }
        size_t o = (((size_t)bh)*MTOT + poff + (size_t)w*W + lane)*HDIM;
        float4* op = (float4*)(g_xw + o);
        #pragma unroll
        for(int c=0;c<8;c++) op[c] = accv[c];
    }
}

// ---------------- gather + average: xf[b,n, h*32+d] ----------------
__global__ void gather_avg_kernel(const int* __restrict__ ridx, const float* __restrict__ cnt_inv, int K){
    int gw = (blockIdx.x*blockDim.x + threadIdx.x) >> 5;
    int lane = threadIdx.x & 31;
    if(gw >= MROWS*NH) return;
    int h  = gw & 7;
    int bn = gw >> 3;
    int n  = bn % NN;
    int b  = bn / NN;
    float acc = 0.f;
    size_t base = ((size_t)(b*NH + h))*MTOT;
    for(int k=0;k<K;k++){
        int r = ridx[(size_t)n*K + k];
        if((unsigned)r < (unsigned)MTOT) acc += g_xw[(base + r)*HDIM + lane];
    }
    g_xf[((size_t)bn)*CIN + h*HDIM + lane] = acc * cnt_inv[n];
}

// ---------------- BN statistics (deterministic two-pass) ----------------
__global__ void bn_part_kernel(){
    int j = threadIdx.x, blk = blockIdx.x;
    const int rows_per = (MROWS + NPART - 1)/NPART;
    int r0 = blk*rows_per;
    int r1 = r0 + rows_per; if(r1 > MROWS) r1 = MROWS;
    float s = 0.f, sq = 0.f;
    for(int r=r0;r<r1;r++){
        float v = g_res2[(size_t)r*COUT + j];
        s += v; sq += v*v;
    }
    g_psum[blk*COUT + j] = s;
    g_psq [blk*COUT + j] = sq;
}

__global__ void bn_final_kernel(const float* __restrict__ gamma, const float* __restrict__ beta){
    int j = threadIdx.x;
    float s = 0.f, sq = 0.f;
    for(int p=0;p<NPART;p++){ s += g_psum[p*COUT + j]; sq += g_psq[p*COUT + j]; }
    float mean = s / (float)MROWS;
    float var  = sq / (float)MROWS - mean*mean;
    float sc = gamma[j] * rsqrtf(var + BN_EPS);
    g_scale[j] = sc;
    g_shift[j] = beta[j] - mean*sc;
}

// ---------------- final: out_t + bn, transposed write (B, OUT, N) ----------------
__global__ void final_out_kernel(float* __restrict__ dout){
    __shared__ float t[32][33];
    const int n0 = blockIdx.x * 32;
    const int by = blockIdx.y;
    const int b  = by >> 3;
    const int j0 = (by & 7) * 32;
    const int txx = threadIdx.x, tyy = threadIdx.y;

    const int j = j0 + txx;
    const float sc = g_scale[j], sh = g_shift[j];
    #pragma unroll
    for(int i=0;i<4;i++){
        int n = n0 + tyy + i*8;
        float v = 0.f;
        if(n < NN){
            size_t idx = ((size_t)(b*NN + n))*COUT + j;
            v = g_out[idx] + g_res2[idx]*sc + sh;
        }
        t[tyy + i*8][txx] = v;
    }
    __syncthreads();
    int n = n0 + txx;
    if(n < NN){
        #pragma unroll
        for(int i=0;i<4;i++){
            int jj = j0 + tyy + i*8;
            dout[((size_t)(b*COUT + jj))*NN + n] = t[txx][tyy + i*8];
        }
    }
}

// ---------------- launch ----------------
extern "C" void kernel_launch(void* const* d_in, const int* in_sizes, int n_in,
                              void* d_out, int out_size){
    (void)out_size;

    // ---- resolve inputs by element count (robust to dict vs sorted-key order) ----
    const int SZ_X = 20972544, SZ_WQKV = 196608, SZ_WM = 131072, SZ_WPR = 65536,
              SZ_BQKV = 768, SZ_BM1 = 512, SZ_CNT = 40962, SZ_TOP = 40992, SZ_DOWN = 48678;

    int ix=-1, iwqkv=-1, iwm1=-1, iwm2=-1, iwproj=-1, iwres=-1, ibqkv=-1, ibm1=-1,
        icnt=-1, itop=-1, idown=-1, irev=-1;
    int i256[8]; int n256 = 0;
    for(int i=0;i<n_in;i++){
        int s = in_sizes[i];
        if(s==SZ_X) ix=i;
        else if(s==SZ_WQKV) iwqkv=i;
        else if(s==SZ_WM){ if(iwm1<0) iwm1=i; else iwm2=i; }
        else if(s==SZ_WPR){ if(iwproj<0) iwproj=i; else iwres=i; }
        else if(s==SZ_BQKV) ibqkv=i;
        else if(s==SZ_BM1) ibm1=i;
        else if(s==SZ_CNT) icnt=i;
        else if(s==SZ_TOP) itop=i;
        else if(s==SZ_DOWN) idown=i;
        else if(s==256){ if(n256<8) i256[n256++]=i; }
        else if(s>SZ_CNT && (s % SZ_CNT)==0) irev=i;
    }

    int ibproj, ibres, ibm2, igamma, ibeta;
    bool resolved = (ix>=0 && iwqkv>=0 && iwm1>=0 && iwm2>=0 && iwproj>=0 && iwres>=0 &&
                     ibqkv>=0 && ibm1>=0 && icnt>=0 && itop>=0 && idown>=0 && irev>=0 && n256>=5);
    if(resolved){
        if(ix != 0){ // sorted-key order: beta, bm2, bproj, bres, gamma
            ibeta=i256[0]; ibm2=i256[1]; ibproj=i256[2]; ibres=i256[3]; igamma=i256[4];
        } else {     // dict order: bproj, bres, bm2, gamma, beta
            ibproj=i256[0]; ibres=i256[1]; ibm2=i256[2]; igamma=i256[3]; ibeta=i256[4];
        }
    } else {
        ix=0; iwqkv=1; ibqkv=2; iwproj=3; ibproj=4; iwres=5; ibres=6;
        iwm1=7; ibm1=8; iwm2=9; ibm2=10; igamma=11; ibeta=12; icnt=13;
        itop=14; idown=15; irev=16;
    }

    const float* x     = (const float*)d_in[ix];
    const float* Wqkv  = (const float*)d_in[iwqkv];
    const float* bqkv  = (const float*)d_in[ibqkv];
    const float* Wproj = (const float*)d_in[iwproj];
    const float* bproj = (const float*)d_in[ibproj];
    const float* Wres  = (const float*)d_in[iwres];
    const float* bres  = (const float*)d_in[ibres];
    const float* Wm1   = (const float*)d_in[iwm1];
    const float* bm1   = (const float*)d_in[ibm1];
    const float* Wm2   = (const float*)d_in[iwm2];
    const float* bm2   = (const float*)d_in[ibm2];
    const float* gamma = (const float*)d_in[igamma];
    const float* beta  = (const float*)d_in[ibeta];
    const float* cnt_inv = (const float*)d_in[icnt];

    int K = in_sizes[irev] / NN;
    if(K < 1) K = 1;
    if(K > KMAX) K = KMAX;

    int* g_top32_p;  cudaGetSymbolAddress((void**)&g_top32_p,  g_top32);
    int* g_down32_p; cudaGetSymbolAddress((void**)&g_down32_p, g_down32);
    int* g_rev32_p;  cudaGetSymbolAddress((void**)&g_rev32_p,  g_rev32);
    float* g_xf_p;   cudaGetSymbolAddress((void**)&g_xf_p,   g_xf);
    float* g_out_p;  cudaGetSymbolAddress((void**)&g_out_p,  g_out);
    float* g_res_p;  cudaGetSymbolAddress((void**)&g_res_p,  g_res);
    float* g_res2_p; cudaGetSymbolAddress((void**)&g_res2_p, g_res2);
    float* g_Wm_p;   cudaGetSymbolAddress((void**)&g_Wm_p,   g_Wm);
    float* g_bm_p;   cudaGetSymbolAddress((void**)&g_bm_p,   g_bm);

    // 0. normalize index dtype (int32 or int64) into int32 scratch
    detect_idx_kernel<<<1, 32>>>((const unsigned int*)d_in[itop]);
    conv_idx_kernel<<<(NTOP*WTOP   + 255)/256, 256>>>(d_in[itop],  g_top32_p,  NTOP*WTOP);
    conv_idx_kernel<<<(NDOWN*WDOWN + 255)/256, 256>>>(d_in[idown], g_down32_p, NDOWN*WDOWN);
    conv_idx_kernel<<<(NN*K        + 255)/256, 256>>>(d_in[irev],  g_rev32_p,  NN*K);

    // 1. fold MLP weights
    fold_mlp_kernel<<<256, 256>>>(Wm1, Wm2, bm1, bm2);

    // 2. qkv + residual projection (tf32 tensor cores)
    {
        dim3 grid((MROWS + 127)/128, 1024/128);
        gemm_qkvres_tc<<<grid, 256, SMEM_BYTES>>>(x, Wqkv, bqkv, Wres, bres);
    }

    // 3. window attention
    attn_kernel<WTOP> <<<dim3(NTOP,  BQ*NH), 32>>>(g_top32_p,  0);
    attn_kernel<WDOWN><<<dim3(NDOWN, BQ*NH), 32>>>(g_down32_p, PTOP);

    // 4. gather + count-average back to node order
    {
        long long warps = (long long)MROWS*NH;
        int blocks = (int)((warps*32 + 255)/256);
        gather_avg_kernel<<<blocks, 256>>>(g_rev32_p, cnt_inv, K);
    }

    // 5. out = xf @ Wproj + bproj + res   (tf32)
    {
        dim3 grid((MROWS + 127)/128, COUT/128);
        gemm_rm_tc<<<grid, 256, SMEM_BYTES>>>(g_xf_p, Wproj, bproj, g_res_p, g_out_p);
    }

    // 6. res2 = out @ Wm + bm (folded MLP, tf32)
    {
        dim3 grid((MROWS + 127)/128, COUT/128);
        gemm_rm_tc<<<grid, 256, SMEM_BYTES>>>(g_out_p, g_Wm_p, g_bm_p, nullptr, g_res2_p);
    }

    // 7-8. batch-norm statistics
    bn_part_kernel<<<NPART, 256>>>();
    bn_final_kernel<<<1, 256>>>(gamma, beta);

    // 9. final transposed output
    {
        dim3 grid((NN + 31)/32, BQ*(COUT/32));
        final_out_kernel<<<grid, dim3(32,8)>>>((float*)d_out);
    }
}

// round 10
// speedup vs baseline: 1.7886x; 1.0553x over previous
#include <cuda_runtime.h>
#include <math.h>
#include <stdint.h>

// ---------------- problem constants ----------------
#define BQ 2
#define CIN 256
#define COUT 256
#define HDIM 32
#define NH 8
#define NN 40962
#define NTOP 2562
#define WTOP 16
#define NDOWN 2562
#define WDOWN 19
#define PTOP (NTOP*WTOP)                 // 40992
#define MTOT (PTOP + NDOWN*WDOWN)        // 89670
#define MROWS (BQ*NN)                    // 81924
#define MLPH 512
#define BN_EPS 1e-5f
#define ATT_SCALE 0.17677669529663687f   // 32^-0.5
#define NPART 641                         // (MROWS+127)/128 m-tiles
#define KMAX 32

// GEMM tile config
#define SSTR 24                           // smem row stride (floats), conflict-free for LDS.64 frags
#define TILE_FLOATS (128*SSTR)            // 3072 floats per buffer
#define SMEM_BYTES (4*TILE_FLOATS*4)      // As0,As1,Bs0,Bs1 = 49152 B

// ---------------- scratch (static device, no runtime alloc) ----------------
__device__ float g_qkv[(size_t)MROWS*768];
__device__ float g_res[(size_t)MROWS*COUT];
__device__ float g_xw [(size_t)BQ*MTOT*256];    // layout [b, r, h*32+d]
__device__ float g_xf [(size_t)MROWS*CIN];
__device__ float g_out[(size_t)MROWS*COUT];
__device__ float g_res2[(size_t)MROWS*COUT];
__device__ float g_Wm[CIN*COUT];
__device__ float g_bm[COUT];
__device__ float g_psum[(size_t)NPART*COUT];
__device__ float g_psq [(size_t)NPART*COUT];
__device__ float g_scale[COUT];
__device__ float g_shift[COUT];
__device__ int   g_is64;
__device__ int   g_top32 [NTOP*WTOP];
__device__ int   g_down32[NDOWN*WDOWN];
__device__ int   g_rev32 [(size_t)NN*KMAX];

// ---------------- helpers ----------------
__device__ __forceinline__ float tf32r(float x){
    uint32_t u; asm("cvt.rna.tf32.f32 %0, %1;" : "=r"(u) : "f"(x));
    return __uint_as_float(u);
}

__device__ __forceinline__ void mma_tf32(float4& d, float2 A0, float2 A1, float2 B0){
    uint32_t a0=__float_as_uint(A0.x), a1=__float_as_uint(A1.x),
             a2=__float_as_uint(A0.y), a3=__float_as_uint(A1.y),
             b0=__float_as_uint(B0.x), b1=__float_as_uint(B0.y);
    asm volatile("mma.sync.aligned.m16n8k8.row.col.f32.tf32.tf32.f32 "
        "{%0,%1,%2,%3},{%4,%5,%6,%7},{%8,%9},{%0,%1,%2,%3};"
        : "+f"(d.x),"+f"(d.y),"+f"(d.z),"+f"(d.w)
        : "r"(a0),"r"(a1),"r"(a2),"r"(a3),"r"(b0),"r"(b1));
}

// compute 2 k-steps of mma over the staged 128x16 (A) and 128x16 (B) tiles
__device__ __forceinline__ void mma_tile(const float* __restrict__ As, const float* __restrict__ Bs,
                                         int warp_m, int warp_n, int group, int qc,
                                         float4 acc[4][4]){
    #pragma unroll
    for(int s=0; s<2; ++s){
        float2 Af[4][2];
        #pragma unroll
        for(int mt=0; mt<4; ++mt){
            int r = warp_m*64 + mt*16 + group;
            Af[mt][0] = *(const float2*)(As + r*SSTR     + s*8 + qc*2);
            Af[mt][1] = *(const float2*)(As + (r+8)*SSTR + s*8 + qc*2);
        }
        float2 Bf[4];
        #pragma unroll
        for(int nt=0; nt<4; ++nt){
            int r = warp_n*32 + nt*8 + group;
            Bf[nt] = *(const float2*)(Bs + r*SSTR + s*8 + qc*2);
        }
        #pragma unroll
        for(int mt=0; mt<4; ++mt)
            #pragma unroll
            for(int nt=0; nt<4; ++nt)
                mma_tf32(acc[mt][nt], Af[mt][0], Af[mt][1], Bf[nt]);
    }
}

__device__ __forceinline__ void sts_tile(float* __restrict__ S, int row, int h, const float v[8]){
    float4 p0 = make_float4(tf32r(v[0]),tf32r(v[1]),tf32r(v[2]),tf32r(v[3]));
    float4 p1 = make_float4(tf32r(v[4]),tf32r(v[5]),tf32r(v[6]),tf32r(v[7]));
    *(float4*)(S + row*SSTR + h*8)     = p0;
    *(float4*)(S + row*SSTR + h*8 + 4) = p1;
}

// ---------------- index dtype sniffing + normalization ----------------
__global__ void detect_idx_kernel(const unsigned int* __restrict__ raw){
    if(threadIdx.x == 0 && blockIdx.x == 0){
        unsigned int acc = 0u;
        for(int i = 0; i < 1024; ++i) acc |= raw[2*i + 1];
        g_is64 = (acc == 0u) ? 1 : 0;
    }
}

__global__ void conv_idx_kernel(const void* __restrict__ src, int* __restrict__ dst, int n){
    int i = blockIdx.x*blockDim.x + threadIdx.x;
    if(i >= n) return;
    long long v;
    if(g_is64) v = ((const long long*)src)[i];
    else       v = (long long)((const int*)src)[i];
    if(v < 0) v = 0;
    if(v > (long long)0x7fffffff) v = 0x7fffffff;
    dst[i] = (int)v;
}

// ---------------- fold MLP: Wm = Wm1 @ Wm2, bm = bm1 @ Wm2 + bm2 ----------------
__global__ void fold_mlp_kernel(const float* __restrict__ Wm1, const float* __restrict__ Wm2,
                                const float* __restrict__ bm1, const float* __restrict__ bm2){
    int i = blockIdx.x;
    int j = threadIdx.x;
    float acc = 0.f;
    for(int h=0; h<MLPH; ++h){
        acc += __ldg(&Wm1[i*MLPH + h]) * __ldg(&Wm2[h*COUT + j]);
    }
    g_Wm[i*COUT + j] = acc;
    if(i == 0){
        float b = bm2[j];
        for(int h=0; h<MLPH; ++h) b += __ldg(&bm1[h]) * __ldg(&Wm2[h*COUT + j]);
        g_bm[j] = b;
    }
}

// ---------------- tf32 GEMM 1: qkv + res from x (A accessed transposed) ----------------
// grid = (8 c-tiles FAST, 641 m-tiles): x streams once, W stays L2-resident.
__global__ __launch_bounds__(256, 2)
void gemm_qkvres_tc(const float* __restrict__ x,
                    const float* __restrict__ Wqkv, const float* __restrict__ bqkv,
                    const float* __restrict__ Wres, const float* __restrict__ bres){
    extern __shared__ float sm[];
    float* Abuf[2] = { sm, sm + TILE_FLOATS };
    float* Bbuf[2] = { sm + 2*TILE_FLOATS, sm + 3*TILE_FLOATS };

    const int c0 = blockIdx.x * 128;
    const int m0 = blockIdx.y * 128;
    const bool isres = (c0 >= 768);
    const float* W   = isres ? Wres : Wqkv;
    const float* bia = isres ? bres : bqkv;
    const int ldw    = isres ? COUT : 768;
    const int cW0    = isres ? c0 - 768 : c0;

    const int tid = threadIdx.x;
    const int wid = tid >> 5, lane = tid & 31;
    const int warp_m = wid >> 2, warp_n = wid & 3;
    const int group = lane >> 2, qc = lane & 3;
    const int lm = tid & 127, h = tid >> 7;

    float4 acc[4][4];
    #pragma unroll
    for(int i=0;i<4;i++)
        #pragma unroll
        for(int j=0;j<4;j++) acc[i][j] = make_float4(0.f,0.f,0.f,0.f);

    float av[8], bv[8];
    // prologue: stage kc=0
    {
        int m = m0 + lm;
        if(m < MROWS){
            int b = (m >= NN) ? 1 : 0;
            int n = m - b*NN;
            const float* xp = x + ((size_t)b*CIN + h*8)*NN + n;
            #pragma unroll
            for(int j=0;j<8;j++) av[j] = xp[(size_t)j*NN];
        } else {
            #pragma unroll
            for(int j=0;j<8;j++) av[j] = 0.f;
        }
        const float* wp = W + (size_t)(h*8)*ldw + cW0 + lm;
        #pragma unroll
        for(int j=0;j<8;j++) bv[j] = wp[(size_t)j*ldw];
        sts_tile(Abuf[0], lm, h, av);
        sts_tile(Bbuf[0], lm, h, bv);
    }
    __syncthreads();

    for(int t=0; t<16; ++t){
        int cur = t & 1, nxt = (t+1) & 1;
        if(t+1 < 16){
            int kc = (t+1)*16;
            int m = m0 + lm;
            if(m < MROWS){
                int b = (m >= NN) ? 1 : 0;
                int n = m - b*NN;
                const float* xp = x + ((size_t)b*CIN + kc + h*8)*NN + n;
                #pragma unroll
                for(int j=0;j<8;j++) av[j] = xp[(size_t)j*NN];
            } else {
                #pragma unroll
                for(int j=0;j<8;j++) av[j] = 0.f;
            }
            const float* wp = W + (size_t)(kc + h*8)*ldw + cW0 + lm;
            #pragma unroll
            for(int j=0;j<8;j++) bv[j] = wp[(size_t)j*ldw];
        }
        mma_tile(Abuf[cur], Bbuf[cur], warp_m, warp_n, group, qc, acc);
        if(t+1 < 16){
            sts_tile(Abuf[nxt], lm, h, av);
            sts_tile(Bbuf[nxt], lm, h, bv);
        }
        __syncthreads();
    }

    // epilogue
    #pragma unroll
    for(int nt=0; nt<4; ++nt){
        int cw = cW0 + warp_n*32 + nt*8 + qc*2;
        float2 bb = *(const float2*)(bia + cw);
        #pragma unroll
        for(int mt=0; mt<4; ++mt){
            int r0 = m0 + warp_m*64 + mt*16 + group;
            float4 a = acc[mt][nt];
            if(r0 < MROWS){
                float2 v = make_float2(a.x + bb.x, a.y + bb.y);
                if(!isres) *(float2*)(g_qkv + (size_t)r0*768  + cw) = v;
                else       *(float2*)(g_res + (size_t)r0*COUT + cw) = v;
            }
            int r1 = r0 + 8;
            if(r1 < MROWS){
                float2 v = make_float2(a.z + bb.x, a.w + bb.y);
                if(!isres) *(float2*)(g_qkv + (size_t)r1*768  + cw) = v;
                else       *(float2*)(g_res + (size_t)r1*COUT + cw) = v;
            }
        }
    }
}

// ---------------- tf32 GEMM 2: row-major A(m,256) @ W(256x256) + bias (+ add) ----------------
// grid = (2 c-tiles FAST, 641 m-tiles). Optional fused BN column partials (deterministic).
__global__ __launch_bounds__(256, 2)
void gemm_rm_tc(const float* __restrict__ A, const float* __restrict__ W,
                const float* __restrict__ bias, const float* __restrict__ addsrc,
                float* __restrict__ Dst, int dobn){
    extern __shared__ float sm[];
    float* Abuf[2] = { sm, sm + TILE_FLOATS };
    float* Bbuf[2] = { sm + 2*TILE_FLOATS, sm + 3*TILE_FLOATS };

    const int c0 = blockIdx.x * 128;
    const int m0 = blockIdx.y * 128;
    const int tid = threadIdx.x;
    const int wid = tid >> 5, lane = tid & 31;
    const int warp_m = wid >> 2, warp_n = wid & 3;
    const int group = lane >> 2, qc = lane & 3;
    const int lm = tid & 127, h = tid >> 7;

    float4 acc[4][4];
    #pragma unroll
    for(int i=0;i<4;i++)
        #pragma unroll
        for(int j=0;j<4;j++) acc[i][j] = make_float4(0.f,0.f,0.f,0.f);

    float av[8], bv[8];
    {
        int m = m0 + lm;
        if(m < MROWS){
            float4 v0 = *(const float4*)(A + (size_t)m*CIN + h*8);
            float4 v1 = *(const float4*)(A + (size_t)m*CIN + h*8 + 4);
            av[0]=v0.x; av[1]=v0.y; av[2]=v0.z; av[3]=v0.w;
            av[4]=v1.x; av[5]=v1.y; av[6]=v1.z; av[7]=v1.w;
        } else {
            #pragma unroll
            for(int j=0;j<8;j++) av[j] = 0.f;
        }
        const float* wp = W + (size_t)(h*8)*COUT + c0 + lm;
        #pragma unroll
        for(int j=0;j<8;j++) bv[j] = wp[(size_t)j*COUT];
        sts_tile(Abuf[0], lm, h, av);
        sts_tile(Bbuf[0], lm, h, bv);
    }
    __syncthreads();

    for(int t=0; t<16; ++t){
        int cur = t & 1, nxt = (t+1) & 1;
        if(t+1 < 16){
            int kc = (t+1)*16;
            int m = m0 + lm;
            if(m < MROWS){
                float4 v0 = *(const float4*)(A + (size_t)m*CIN + kc + h*8);
                float4 v1 = *(const float4*)(A + (size_t)m*CIN + kc + h*8 + 4);
                av[0]=v0.x; av[1]=v0.y; av[2]=v0.z; av[3]=v0.w;
                av[4]=v1.x; av[5]=v1.y; av[6]=v1.z; av[7]=v1.w;
            } else {
                #pragma unroll
                for(int j=0;j<8;j++) av[j] = 0.f;
            }
            const float* wp = W + (size_t)(kc + h*8)*COUT + c0 + lm;
            #pragma unroll
            for(int j=0;j<8;j++) bv[j] = wp[(size_t)j*COUT];
        }
        mma_tile(Abuf[cur], Bbuf[cur], warp_m, warp_n, group, qc, acc);
        if(t+1 < 16){
            sts_tile(Abuf[nxt], lm, h, av);
            sts_tile(Bbuf[nxt], lm, h, bv);
        }
        __syncthreads();
    }

    float tsum[4][2], tsq[4][2];
    #pragma unroll
    for(int nt=0; nt<4; ++nt){ tsum[nt][0]=tsum[nt][1]=tsq[nt][0]=tsq[nt][1]=0.f; }

    #pragma unroll
    for(int nt=0; nt<4; ++nt){
        int cw = c0 + warp_n*32 + nt*8 + qc*2;
        float2 bb = *(const float2*)(bias + cw);
        #pragma unroll
        for(int mt=0; mt<4; ++mt){
            int r0 = m0 + warp_m*64 + mt*16 + group;
            float4 a = acc[mt][nt];
            if(r0 < MROWS){
                float2 v = make_float2(a.x + bb.x, a.y + bb.y);
                if(addsrc){
                    float2 ad = *(const float2*)(addsrc + (size_t)r0*COUT + cw);
                    v.x += ad.x; v.y += ad.y;
                }
                *(float2*)(Dst + (size_t)r0*COUT + cw) = v;
                tsum[nt][0] += v.x; tsum[nt][1] += v.y;
                tsq[nt][0]  += v.x*v.x; tsq[nt][1] += v.y*v.y;
            }
            int r1 = r0 + 8;
            if(r1 < MROWS){
                float2 v = make_float2(a.z + bb.x, a.w + bb.y);
                if(addsrc){
                    float2 ad = *(const float2*)(addsrc + (size_t)r1*COUT + cw);
                    v.x += ad.x; v.y += ad.y;
                }
                *(float2*)(Dst + (size_t)r1*COUT + cw) = v;
                tsum[nt][0] += v.x; tsum[nt][1] += v.y;
                tsq[nt][0]  += v.x*v.x; tsq[nt][1] += v.y*v.y;
            }
        }
    }

    if(dobn){
        // reduce over the 8 'group' lanes (xor orbit stride 4,8,16) -> 64-row partials per warp
        __syncthreads();                 // tile buffers free after mainloop
        float* s_sum = sm;               // [2][128]
        float* s_sq  = sm + 256;         // [2][128]
        #pragma unroll
        for(int nt=0; nt<4; ++nt){
            #pragma unroll
            for(int j=0; j<2; ++j){
                float s = tsum[nt][j], q = tsq[nt][j];
                s += __shfl_xor_sync(0xffffffffu, s, 4);
                q += __shfl_xor_sync(0xffffffffu, q, 4);
                s += __shfl_xor_sync(0xffffffffu, s, 8);
                q += __shfl_xor_sync(0xffffffffu, q, 8);
                s += __shfl_xor_sync(0xffffffffu, s, 16);
                q += __shfl_xor_sync(0xffffffffu, q, 16);
                if(lane < 4){
                    int cl = warp_n*32 + nt*8 + qc*2 + j;
                    s_sum[warp_m*128 + cl] = s;
                    s_sq [warp_m*128 + cl] = q;
                }
            }
        }
        __syncthreads();
        if(tid < 128){
            size_t o = (size_t)blockIdx.y*COUT + c0 + tid;
            g_psum[o] = s_sum[tid] + s_sum[128 + tid];
            g_psq [o] = s_sq [tid] + s_sq [128 + tid];
        }
    }
}

// ---------------- window attention: one warp per (window, b, h) ----------------
// writes g_xw in [b, r, h*32+d] layout
template<int W>
__global__ void attn_kernel(const int* __restrict__ widx, int poff){
    const int w  = blockIdx.x;
    const int bh = blockIdx.y;
    const int b  = bh >> 3;
    const int h  = bh & 7;
    const int lane = threadIdx.x;

    __shared__ int    nidx[W];
    __shared__ float4 ks4[W*8];
    __shared__ float4 vs4[W*8];

    if(lane < W){
        int v = widx[w*W + lane];
        if((unsigned)v >= (unsigned)NN) v = 0;
        nidx[lane] = v;
    }
    __syncwarp();

    for(int t = lane; t < W*8; t += 32){
        int r = t >> 3, c4 = t & 7;
        size_t base = ((size_t)(b*NN + nidx[r]))*768 + h*HDIM + c4*4;
        ks4[t] = *(const float4*)(g_qkv + base + 256);
        vs4[t] = *(const float4*)(g_qkv + base + 512);
    }
    __syncwarp();

    if(lane < W){
        float4 qv[8];
        {
            size_t base = ((size_t)(b*NN + nidx[lane]))*768 + h*HDIM;
            const float4* qp = (const float4*)(g_qkv + base);
            #pragma unroll
            for(int c=0;c<8;c++) qv[c] = qp[c];
        }
        float p[W];
        float mx = -1e30f;
        #pragma unroll
        for(int j=0;j<W;j++){
            const float4* kp = ks4 + j*8;
            float s = 0.f;
            #pragma unroll
            for(int c=0;c<8;c++){
                float4 kk = kp[c];
                s += qv[c].x*kk.x + qv[c].y*kk.y + qv[c].z*kk.z + qv[c].w*kk.w;
            }
            s *= ATT_SCALE;
            p[j] = s;
            mx = fmaxf(mx, s);
        }
        float sum = 0.f;
        #pragma unroll
        for(int j=0;j<W;j++){ p[j] = __expf(p[j]-mx); sum += p[j]; }
        float inv = 1.f/sum;
        float4 accv[8];
        #pragma unroll
        for(int c=0;c<8;c++) accv[c] = make_float4(0.f,0.f,0.f,0.f);
        #pragma unroll
        for(int j=0;j<W;j++){
            float a = p[j]*inv;
            const float4* vp = vs4 + j*8;
            #pragma unroll
            for(int c=0;c<8;c++){
                float4 vv = vp[c];
                accv[c].x += a*vv.x; accv[c].y += a*vv.y;
                accv[c].z += a*vv.z; accv[c].w += a*vv.w;
            }
        }
        size_t o = ((size_t)(b*MTOT + poff + w*W + lane))*256 + h*HDIM;
        float4* op = (float4*)(g_xw + o);
        #pragma unroll
        for(int c=0;c<8;c++) op[c] = accv[c];
    }
}

// ---------------- gather + average: block per (b,n), coalesced 1KB window rows ----------------
__global__ __launch_bounds__(256)
void gather_avg_kernel(const int* __restrict__ ridx, const float* __restrict__ cnt_inv, int K){
    const int bn = blockIdx.x;
    const int n  = (bn >= NN) ? bn - NN : bn;
    const int b  = (bn >= NN) ? 1 : 0;
    const int tid = threadIdx.x;

    __shared__ int sidx[KMAX];
    if(tid < K) sidx[tid] = ridx[(size_t)n*K + tid];
    __syncthreads();

    float acc = 0.f;
    const size_t base = (size_t)b*MTOT*256;
    for(int k=0;k<K;k++){
        int r = sidx[k];
        if((unsigned)r < (unsigned)MTOT)
            acc += g_xw[base + (size_t)r*256 + tid];
    }
    g_xf[(size_t)bn*CIN + tid] = acc * __ldg(&cnt_inv[n]);
}

// ---------------- BN finalize from fused partials ----------------
__global__ void bn_final_kernel(const float* __restrict__ gamma, const float* __restrict__ beta){
    int j = threadIdx.x;
    float s = 0.f, sq = 0.f;
    for(int p=0;p<NPART;p++){ s += g_psum[(size_t)p*COUT + j]; sq += g_psq[(size_t)p*COUT + j]; }
    float mean = s / (float)MROWS;
    float var  = sq / (float)MROWS - mean*mean;
    float sc = gamma[j] * rsqrtf(var + BN_EPS);
    g_scale[j] = sc;
    g_shift[j] = beta[j] - mean*sc;
}

// ---------------- final: out_t + bn, transposed write (B, OUT, N) ----------------
__global__ void final_out_kernel(float* __restrict__ dout){
    __shared__ float t[32][33];
    const int n0 = blockIdx.x * 32;
    const int by = blockIdx.y;
    const int b  = by >> 3;
    const int j0 = (by & 7) * 32;
    const int txx = threadIdx.x, tyy = threadIdx.y;

    const int j = j0 + txx;
    const float sc = g_scale[j], sh = g_shift[j];
    #pragma unroll
    for(int i=0;i<4;i++){
        int n = n0 + tyy + i*8;
        float v = 0.f;
        if(n < NN){
            size_t idx = ((size_t)(b*NN + n))*COUT + j;
            v = g_out[idx] + g_res2[idx]*sc + sh;
        }
        t[tyy + i*8][txx] = v;
    }
    __syncthreads();
    int n = n0 + txx;
    if(n < NN){
        #pragma unroll
        for(int i=0;i<4;i++){
            int jj = j0 + tyy + i*8;
            dout[((size_t)(b*COUT + jj))*NN + n] = t[txx][tyy + i*8];
        }
    }
}

// ---------------- launch ----------------
extern "C" void kernel_launch(void* const* d_in, const int* in_sizes, int n_in,
                              void* d_out, int out_size){
    (void)out_size;

    // ---- resolve inputs by element count (robust to dict vs sorted-key order) ----
    const int SZ_X = 20972544, SZ_WQKV = 196608, SZ_WM = 131072, SZ_WPR = 65536,
              SZ_BQKV = 768, SZ_BM1 = 512, SZ_CNT = 40962, SZ_TOP = 40992, SZ_DOWN = 48678;

    int ix=-1, iwqkv=-1, iwm1=-1, iwm2=-1, iwproj=-1, iwres=-1, ibqkv=-1, ibm1=-1,
        icnt=-1, itop=-1, idown=-1, irev=-1;
    int i256[8]; int n256 = 0;
    for(int i=0;i<n_in;i++){
        int s = in_sizes[i];
        if(s==SZ_X) ix=i;
        else if(s==SZ_WQKV) iwqkv=i;
        else if(s==SZ_WM){ if(iwm1<0) iwm1=i; else iwm2=i; }
        else if(s==SZ_WPR){ if(iwproj<0) iwproj=i; else iwres=i; }
        else if(s==SZ_BQKV) ibqkv=i;
        else if(s==SZ_BM1) ibm1=i;
        else if(s==SZ_CNT) icnt=i;
        else if(s==SZ_TOP) itop=i;
        else if(s==SZ_DOWN) idown=i;
        else if(s==256){ if(n256<8) i256[n256++]=i; }
        else if(s>SZ_CNT && (s % SZ_CNT)==0) irev=i;
    }

    int ibproj, ibres, ibm2, igamma, ibeta;
    bool resolved = (ix>=0 && iwqkv>=0 && iwm1>=0 && iwm2>=0 && iwproj>=0 && iwres>=0 &&
                     ibqkv>=0 && ibm1>=0 && icnt>=0 && itop>=0 && idown>=0 && irev>=0 && n256>=5);
    if(resolved){
        if(ix != 0){ // sorted-key order: beta, bm2, bproj, bres, gamma
            ibeta=i256[0]; ibm2=i256[1]; ibproj=i256[2]; ibres=i256[3]; igamma=i256[4];
        } else {     // dict order: bproj, bres, bm2, gamma, beta
            ibproj=i256[0]; ibres=i256[1]; ibm2=i256[2]; igamma=i256[3]; ibeta=i256[4];
        }
    } else {
        ix=0; iwqkv=1; ibqkv=2; iwproj=3; ibproj=4; iwres=5; ibres=6;
        iwm1=7; ibm1=8; iwm2=9; ibm2=10; igamma=11; ibeta=12; icnt=13;
        itop=14; idown=15; irev=16;
    }

    const float* x     = (const float*)d_in[ix];
    const float* Wqkv  = (const float*)d_in[iwqkv];
    const float* bqkv  = (const float*)d_in[ibqkv];
    const float* Wproj = (const float*)d_in[iwproj];
    const float* bproj = (const float*)d_in[ibproj];
    const float* Wres  = (const float*)d_in[iwres];
    const float* bres  = (const float*)d_in[ibres];
    const float* Wm1   = (const float*)d_in[iwm1];
    const float* bm1   = (const float*)d_in[ibm1];
    const float* Wm2   = (const float*)d_in[iwm2];
    const float* bm2   = (const float*)d_in[ibm2];
    const float* gamma = (const float*)d_in[igamma];
    const float* beta  = (const float*)d_in[ibeta];
    const float* cnt_inv = (const float*)d_in[icnt];

    int K = in_sizes[irev] / NN;
    if(K < 1) K = 1;
    if(K > KMAX) K = KMAX;

    int* g_top32_p;  cudaGetSymbolAddress((void**)&g_top32_p,  g_top32);
    int* g_down32_p; cudaGetSymbolAddress((void**)&g_down32_p, g_down32);
    int* g_rev32_p;  cudaGetSymbolAddress((void**)&g_rev32_p,  g_rev32);
    float* g_xf_p;   cudaGetSymbolAddress((void**)&g_xf_p,   g_xf);
    float* g_out_p;  cudaGetSymbolAddress((void**)&g_out_p,  g_out);
    float* g_res_p;  cudaGetSymbolAddress((void**)&g_res_p,  g_res);
    float* g_res2_p; cudaGetSymbolAddress((void**)&g_res2_p, g_res2);
    float* g_Wm_p;   cudaGetSymbolAddress((void**)&g_Wm_p,   g_Wm);
    float* g_bm_p;   cudaGetSymbolAddress((void**)&g_bm_p,   g_bm);

    // 0. normalize index dtype (int32 or int64) into int32 scratch
    detect_idx_kernel<<<1, 32>>>((const unsigned int*)d_in[itop]);
    conv_idx_kernel<<<(NTOP*WTOP   + 255)/256, 256>>>(d_in[itop],  g_top32_p,  NTOP*WTOP);
    conv_idx_kernel<<<(NDOWN*WDOWN + 255)/256, 256>>>(d_in[idown], g_down32_p, NDOWN*WDOWN);
    conv_idx_kernel<<<(NN*K        + 255)/256, 256>>>(d_in[irev],  g_rev32_p,  NN*K);

    // 1. fold MLP weights
    fold_mlp_kernel<<<256, 256>>>(Wm1, Wm2, bm1, bm2);

    // 2. qkv + residual projection (tf32 tensor cores, c-fast grid: x streams once)
    {
        dim3 grid(1024/128, (MROWS + 127)/128);
        gemm_qkvres_tc<<<grid, 256, SMEM_BYTES>>>(x, Wqkv, bqkv, Wres, bres);
    }

    // 3. window attention
    attn_kernel<WTOP> <<<dim3(NTOP,  BQ*NH), 32>>>(g_top32_p,  0);
    attn_kernel<WDOWN><<<dim3(NDOWN, BQ*NH), 32>>>(g_down32_p, PTOP);

    // 4. gather + count-average back to node order (coalesced 1KB rows)
    gather_avg_kernel<<<MROWS, 256>>>(g_rev32_p, cnt_inv, K);

    // 5. out = xf @ Wproj + bproj + res   (tf32)
    {
        dim3 grid(COUT/128, (MROWS + 127)/128);
        gemm_rm_tc<<<grid, 256, SMEM_BYTES>>>(g_xf_p, Wproj, bproj, g_res_p, g_out_p, 0);
    }

    // 6. res2 = out @ Wm + bm (folded MLP, tf32) + fused BN partials
    {
        dim3 grid(COUT/128, (MROWS + 127)/128);
        gemm_rm_tc<<<grid, 256, SMEM_BYTES>>>(g_out_p, g_Wm_p, g_bm_p, nullptr, g_res2_p, 1);
    }

    // 7. batch-norm finalize
    bn_final_kernel<<<1, 256>>>(gamma, beta);

    // 8. final transposed output
    {
        dim3 grid((NN + 31)/32, BQ*(COUT/32));
        final_out_kernel<<<grid, dim3(32,8)>>>((float*)d_out);
    }
}